// round 4
// baseline (speedup 1.0000x reference)
#include <cuda_runtime.h>
#include <cstdint>

// Problem constants (fixed shapes for this problem instance)
#define BB      4
#define NFULL   65536
#define NSMALL  32768
#define KK      32768
#define FF      256
#define CAP     16      // max copy-events per target vertex (Poisson(0.5) -> max ~8)

// Scratch (device globals; zero-initialized at module load).
// Invariant at entry of every kernel_launch call: d_cnt == 0, d_inv == 0.
// k_gather restores this invariant at the end of each call.
__device__ int  d_cnt  [BB * NFULL];           // events targeting vertex v
__device__ int2 d_slots[BB * NFULL * CAP];     // {.x = time s, .y = source vertex f}
__device__ int  d_inv  [BB * NFULL];           // vertex -> (row in images)+1, or 0
__device__ int  d_src  [BB * NFULL];           // final source row per output vertex (-1 => zero)

// First BB*NSMALL threads: build inverse mask map. Next BB*KK: bucket copy events.
__global__ void k_build(const int* __restrict__ mask_idx, const int* __restrict__ order) {
    int i = blockIdx.x * blockDim.x + threadIdx.x;
    if (i < BB * NSMALL) {
        int b = i / NSMALL, p = i % NSMALL;
        int v = __ldg(&mask_idx[i]);               // sorted unique -> no conflicts
        d_inv[b * NFULL + v] = p + 1;              // +1 so that 0 == "not masked"
    } else {
        int j = i - BB * NSMALL;
        if (j < BB * KK) {
            int b = j / KK, k = j % KK;
            int f = __ldg(&order[b * 2 * KK + k]);        // order[b,0,k]
            int t = __ldg(&order[b * 2 * KK + KK + k]);   // order[b,1,k]
            int s = KK - 1 - k;                    // execution time: k=KK-1 runs first (s=0)
            int idx = b * NFULL + t;
            int slot = atomicAdd(&d_cnt[idx], 1);
            if (slot < CAP) d_slots[idx * CAP + slot] = make_int2(s, f);
        }
    }
}

// Per output vertex: chase provenance backward through copy events.
// Each hop moves to a strictly earlier execution time -> guaranteed termination.
__global__ void k_resolve() {
    int i = blockIdx.x * blockDim.x + threadIdx.x;
    if (i >= BB * NFULL) return;
    int base = (i / NFULL) * NFULL;
    int v = i - base;
    int s = 0x7fffffff;
    for (;;) {
        int idx = base + v;
        int c = d_cnt[idx];
        if (c > CAP) c = CAP;
        int bs = -1, bf = 0;
        #pragma unroll 4
        for (int j = 0; j < c; j++) {
            int2 e = d_slots[idx * CAP + j];
            if (e.x < s && e.x > bs) { bs = e.x; bf = e.y; }
        }
        if (bs < 0) break;       // no earlier write to v: v holds its initial value
        v = bf; s = bs;
    }
    d_src[i] = d_inv[base + v] - 1;   // -1 => masked-out (zero row)
}

// 8 threads per row, 8 float4 per thread (8 independent LDG.128 in flight).
// Row = 64 float4; thread t handles float4 indices {t, t+8, ..., t+56}:
// each batch of 8 threads covers a contiguous 128B line -> fully coalesced.
// Output stores use .cs (evict-first): zero reuse, keep L2 for image reads.
// Lane 0 of each row also resets d_cnt/d_inv for the next call.
__global__ void k_gather(const float4* __restrict__ img, float4* __restrict__ out) {
    int lane = threadIdx.x & 7;
    int ri   = blockIdx.x * 32 + (threadIdx.x >> 3);  // row index in [0, BB*NFULL)
    int src  = d_src[ri];
    int b    = ri >> 16;                              // NFULL = 65536

    if (lane == 0) { d_cnt[ri] = 0; d_inv[ri] = 0; }  // restore clean state

    float4 v[8];
    #pragma unroll
    for (int j = 0; j < 8; j++) v[j] = make_float4(0.f, 0.f, 0.f, 0.f);
    if (src >= 0) {
        const float4* s = img + (size_t)(b * NSMALL + src) * (FF / 4) + lane;
        #pragma unroll
        for (int j = 0; j < 8; j++) v[j] = s[j * 8];
    }
    float4* o = out + (size_t)ri * (FF / 4) + lane;
    #pragma unroll
    for (int j = 0; j < 8; j++) __stcs(&o[j * 8], v[j]);
}

extern "C" void kernel_launch(void* const* d_in, const int* in_sizes, int n_in,
                              void* d_out, int out_size) {
    const float* images   = (const float*)d_in[0];
    const int*   mask_idx = (const int*)  d_in[1];
    const int*   order    = (const int*)  d_in[2];
    // d_in[3] = n_full (constant 65536, unused)

    k_build  <<<(BB * NSMALL + BB * KK + 255) / 256, 256>>>(mask_idx, order);
    k_resolve<<<(BB * NFULL + 255) / 256, 256>>>();
    k_gather <<<BB * NFULL / 32, 256>>>((const float4*)images, (float4*)d_out);
}

// round 6
// speedup vs baseline: 1.0687x; 1.0687x over previous
#include <cuda_runtime.h>
#include <cstdint>

// Problem constants (fixed shapes for this problem instance)
#define BB      4
#define NFULL   65536
#define NSMALL  32768
#define KK      32768
#define FF      256
#define CAP     16      // max copy-events per target vertex (Poisson(0.5) -> max ~8)

// Scratch (device globals; zero-initialized at module load).
// Invariant at entry of every kernel_launch call: d_cnt == 0, d_inv == 0.
// k_gather restores this invariant on every call (lane 0 per row).
__device__ int  d_cnt  [BB * NFULL];           // events targeting vertex v
__device__ int2 d_slots[BB * NFULL * CAP];     // {.x = time s, .y = source vertex f}
__device__ int  d_inv  [BB * NFULL];           // vertex -> (row in images)+1, or 0
__device__ int  d_src  [BB * NFULL];           // final source row per output vertex (-1 => zero)

// First BB*NSMALL threads: build inverse mask map. Next BB*KK: bucket copy events.
__global__ void k_build(const int* __restrict__ mask_idx, const int* __restrict__ order) {
    int i = blockIdx.x * blockDim.x + threadIdx.x;
    if (i < BB * NSMALL) {
        int b = i / NSMALL, p = i % NSMALL;
        int v = __ldg(&mask_idx[i]);               // sorted unique -> no conflicts
        d_inv[b * NFULL + v] = p + 1;              // +1 so that 0 == "not masked"
    } else {
        int j = i - BB * NSMALL;
        if (j < BB * KK) {
            int b = j / KK, k = j % KK;
            int f = __ldg(&order[b * 2 * KK + k]);        // order[b,0,k]
            int t = __ldg(&order[b * 2 * KK + KK + k]);   // order[b,1,k]
            int s = KK - 1 - k;                    // execution time: k=KK-1 runs first (s=0)
            int idx = b * NFULL + t;
            int slot = atomicAdd(&d_cnt[idx], 1);
            if (slot < CAP) d_slots[idx * CAP + slot] = make_int2(s, f);
        }
    }
}

// Per output vertex: chase provenance backward through copy events.
// Each hop moves to a strictly earlier execution time -> guaranteed termination.
__global__ void k_resolve() {
    int i = blockIdx.x * blockDim.x + threadIdx.x;
    if (i >= BB * NFULL) return;
    int base = (i / NFULL) * NFULL;
    int v = i - base;
    int s = 0x7fffffff;
    for (;;) {
        int idx = base + v;
        int c = d_cnt[idx];
        if (c > CAP) c = CAP;
        int bs = -1, bf = 0;
        #pragma unroll 4
        for (int j = 0; j < c; j++) {
            int2 e = d_slots[idx * CAP + j];
            if (e.x < s && e.x > bs) { bs = e.x; bf = e.y; }
        }
        if (bs < 0) break;       // no earlier write to v: v holds its initial value
        v = bf; s = bs;
    }
    d_src[i] = d_inv[base + v] - 1;   // -1 => masked-out (zero row)
}

// 16 threads per row, 4 float4 per thread (4 independent LDG.128 in flight).
// Row = 64 float4; thread t handles float4 indices {t, t+16, t+32, t+48}:
// each batch of 16 threads covers a contiguous 256B segment -> fully coalesced.
// Lane 0 of each row also resets d_cnt/d_inv for the next call.
__global__ void k_gather(const float4* __restrict__ img, float4* __restrict__ out) {
    int lane = threadIdx.x & 15;
    int ri   = blockIdx.x * 16 + (threadIdx.x >> 4);  // row index in [0, BB*NFULL)
    int src  = d_src[ri];
    int b    = ri >> 16;                              // NFULL = 65536

    if (lane == 0) { d_cnt[ri] = 0; d_inv[ri] = 0; }  // restore clean state

    float4 v0 = make_float4(0.f, 0.f, 0.f, 0.f);
    float4 v1 = v0, v2 = v0, v3 = v0;
    if (src >= 0) {
        const float4* s = img + (size_t)(b * NSMALL + src) * (FF / 4) + lane;
        v0 = s[0]; v1 = s[16]; v2 = s[32]; v3 = s[48];
    }
    float4* o = out + (size_t)ri * (FF / 4) + lane;
    o[0]  = v0;
    o[16] = v1;
    o[32] = v2;
    o[48] = v3;
}

extern "C" void kernel_launch(void* const* d_in, const int* in_sizes, int n_in,
                              void* d_out, int out_size) {
    const float* images   = (const float*)d_in[0];
    const int*   mask_idx = (const int*)  d_in[1];
    const int*   order    = (const int*)  d_in[2];
    // d_in[3] = n_full (constant 65536, unused)

    k_build  <<<(BB * NSMALL + BB * KK + 255) / 256, 256>>>(mask_idx, order);
    k_resolve<<<(BB * NFULL + 255) / 256, 256>>>();
    k_gather <<<BB * NFULL / 16, 256>>>((const float4*)images, (float4*)d_out);
}